// round 11
// baseline (speedup 1.0000x reference)
#include <cuda_runtime.h>
#include <cuda_bf16.h>
#include <cstdint>

#define N_DIM 4096
#define D_DIM 256
#define TILE  128
#define GRID_TILES (N_DIM / TILE)       // 32
#define NUM_CTAS   272                  // sum_{i=0..15} (32 - 2i)

// ---------------- device scratch ----------------
__device__ __nv_bfloat16 g_xb[N_DIM * D_DIM];     // 2 MB bf16 copy of x
__device__ float g_sq[N_DIM];                      // row squared norms
__device__ float g_svec_partial[512][D_DIM];       // colsum partials
__device__ float g_inv;                            // 1 / (2 * sigma^2)

// ---------------- helpers ----------------
__device__ __forceinline__ uint32_t smem_to_u32(const void* p) {
    uint32_t a;
    asm("{ .reg .u64 t; cvta.to.shared.u64 t, %1; cvt.u32.u64 %0, t; }" : "=r"(a) : "l"(p));
    return a;
}

__device__ __forceinline__ void ldsm_x4(uint32_t r[4], uint32_t addr) {
    asm volatile("ldmatrix.sync.aligned.m8n8.x4.shared.b16 {%0,%1,%2,%3}, [%4];"
                 : "=r"(r[0]), "=r"(r[1]), "=r"(r[2]), "=r"(r[3]) : "r"(addr));
}

__device__ __forceinline__ void mma_16816_bf16(float c[4], const uint32_t a[4],
                                               uint32_t b0, uint32_t b1) {
    asm volatile(
        "mma.sync.aligned.m16n8k16.row.col.f32.bf16.bf16.f32 "
        "{%0,%1,%2,%3}, {%4,%5,%6,%7}, {%8,%9}, {%0,%1,%2,%3};"
        : "+f"(c[0]), "+f"(c[1]), "+f"(c[2]), "+f"(c[3])
        : "r"(a[0]), "r"(a[1]), "r"(a[2]), "r"(a[3]), "r"(b0), "r"(b1));
}

#define CP_ASYNC_16(dst, src) \
    asm volatile("cp.async.cg.shared.global [%0], [%1], 16;" :: "r"(dst), "l"(src))
#define CP_ASYNC_COMMIT() asm volatile("cp.async.commit_group;" ::: "memory")
#define CP_ASYNC_WAIT(n)  asm volatile("cp.async.wait_group %0;" :: "n"(n) : "memory")

// ---------------- kernel 1: bf16 convert + row norms + colsum partials --------
__global__ void prep_kernel(const float* __restrict__ x) {
    const int tid  = threadIdx.x;
    const int wid  = tid >> 5;            // 0..15
    const int lane = tid & 31;
    const int row  = blockIdx.x * 16 + wid;

    {
        const float4* src = reinterpret_cast<const float4*>(x + (size_t)row * D_DIM);
        uint2* dst = reinterpret_cast<uint2*>(g_xb + (size_t)row * D_DIM);
        float s = 0.f;
        #pragma unroll
        for (int i = 0; i < 2; i++) {
            float4 v = src[lane + i * 32];
            s += v.x * v.x + v.y * v.y + v.z * v.z + v.w * v.w;
            __nv_bfloat162 lo = __float22bfloat162_rn(make_float2(v.x, v.y));
            __nv_bfloat162 hi = __float22bfloat162_rn(make_float2(v.z, v.w));
            dst[lane + i * 32] = make_uint2(*reinterpret_cast<uint32_t*>(&lo),
                                            *reinterpret_cast<uint32_t*>(&hi));
        }
        #pragma unroll
        for (int o = 16; o; o >>= 1) s += __shfl_xor_sync(0xffffffffu, s, o);
        if (lane == 0) g_sq[row] = s;
    }
    const int col = tid & 255;
    const int h   = tid >> 8;
    const float* base = x + ((size_t)blockIdx.x * 16 + h * 8) * D_DIM + col;
    float acc = 0.f;
    #pragma unroll
    for (int r = 0; r < 8; r++) acc += base[r * D_DIM];
    g_svec_partial[blockIdx.x * 2 + h][col] = acc;
}

// ---------------- kernel 2: sigma -> g_inv ----------------
__global__ void sigma_kernel() {
    const int t   = threadIdx.x;      // 1024 threads
    const int col = t & 255;
    const int grp = t >> 8;           // 4 groups of 128 partial-rows

    float scp = 0.f;
    #pragma unroll 8
    for (int b = grp * 128; b < grp * 128 + 128; b++) scp += g_svec_partial[b][col];

    __shared__ float sh_sc[4][256];
    sh_sc[grp][col] = scp;

    double sq = 0.0;
    #pragma unroll
    for (int k = 0; k < 4; k++) sq += (double)g_sq[t + k * 1024];

    __shared__ double sh[1024];
    sh[t] = sq;
    __syncthreads();

    __shared__ double sh_ss[256];
    if (t < 256) {
        double sc = (double)sh_sc[0][t] + (double)sh_sc[1][t]
                  + (double)sh_sc[2][t] + (double)sh_sc[3][t];
        sh_ss[t] = sc * sc;
    }
    __syncthreads();

    for (int o = 512; o; o >>= 1) {
        if (t < o) sh[t] += sh[t + o];
        if (o <= 128 && t < o) sh_ss[t] += sh_ss[t + o];
        __syncthreads();
    }
    if (t == 0) {
        const double N = (double)N_DIM;
        double mean_d2 = 2.0 * sh[0] / N - 2.0 * sh_ss[0] / (N * N);
        g_inv = (float)(1.0 / (2.0 * mean_d2));  // ALPHA = 1
    }
}

// ---------------- kernel 3: fused symmetric GEMM + d2 + exp -------------------
// CTA tile 256x128, 512 threads, 4x4 warps (warp tile 64x32). K in 4 chunks of
// 64, 3-stage cp.async pipeline, one sync per chunk, register-level frag
// double-buffering (A per-mi, B per-ks).
#define NTHREADS   512
#define CHUNK_K    64
#define NCHUNK     (D_DIM / CHUNK_K)     // 4
#define NSTAGE     3
#define CROW_BYTES 144
#define A_ROWS     256
#define B_ROWS     128
#define SA_BYTES   (A_ROWS * CROW_BYTES)          // 36864
#define SB_BYTES   (B_ROWS * CROW_BYTES)          // 18432
#define STAGE_BYTES (SA_BYTES + SB_BYTES)         // 55296
#define GEMM_SMEM  (NSTAGE * STAGE_BYTES)         // 165888
#define T_ST 132

__device__ __forceinline__ void load_chunk_fn(uint32_t smem_u, int tid,
                                              const __nv_bfloat16* gA,
                                              const __nv_bfloat16* gB,
                                              int c, int stage) {
    const uint32_t sA = smem_u + stage * STAGE_BYTES;
    const uint32_t sB = sA + SA_BYTES;
    #pragma unroll
    for (int it = 0; it < 4; it++) {
        int idx = tid + it * NTHREADS;
        int r = idx >> 3, q = idx & 7;
        CP_ASYNC_16(sA + (uint32_t)r * CROW_BYTES + (uint32_t)q * 16,
                    gA + (size_t)r * D_DIM + c * CHUNK_K + q * 8);
    }
    #pragma unroll
    for (int it = 0; it < 2; it++) {
        int idx = tid + it * NTHREADS;
        int r = idx >> 3, q = idx & 7;
        CP_ASYNC_16(sB + (uint32_t)r * CROW_BYTES + (uint32_t)q * 16,
                    gB + (size_t)r * D_DIM + c * CHUNK_K + q * 8);
    }
    CP_ASYNC_COMMIT();
}

__global__ __launch_bounds__(NTHREADS, 1)
void gemm_fused_kernel(float* __restrict__ d_out) {
    extern __shared__ char smem[];
    const uint32_t smem_u = smem_to_u32(smem);

    const int tid  = threadIdx.x;
    const int wid  = tid >> 5;
    const int lane = tid & 31;

    // decode (strip si, col tile j): strip si has 32-2*si tiles, j = 2*si + b
    int b = blockIdx.x, si = 0, rem = 32;
    while (b >= rem) { b -= rem; rem -= 2; si++; }
    const int j = 2 * si + b;
    const int row0 = si * 256;
    const int col0 = j * TILE;
    const bool mirror = (j >= 2 * si + 2);

    const __nv_bfloat16* gA = g_xb + (size_t)row0 * D_DIM;
    const __nv_bfloat16* gB = g_xb + (size_t)col0 * D_DIM;

    const int warp_m = wid & 3;
    const int warp_n = wid >> 2;
    const int m0 = warp_m * 64;
    const int n0 = warp_n * 32;

    float acc[4][4][4];
    #pragma unroll
    for (int mi = 0; mi < 4; mi++)
        #pragma unroll
        for (int ni = 0; ni < 4; ni++)
            #pragma unroll
            for (int q = 0; q < 4; q++) acc[mi][ni][q] = 0.f;

    const uint32_t a_row = (uint32_t)(lane & 15);
    const uint32_t a_kof = (uint32_t)((lane >> 4) << 3);
    const uint32_t b_row = (uint32_t)(((lane >> 4) << 3) + (lane & 7));
    const uint32_t b_kof = (uint32_t)(((lane >> 3) & 1) << 3);

    load_chunk_fn(smem_u, tid, gA, gB, 0, 0);

    #pragma unroll 1
    for (int c = 0; c < NCHUNK; c++) {
        const int stage = c % NSTAGE;
        if (c + 1 < NCHUNK) {
            load_chunk_fn(smem_u, tid, gA, gB, c + 1, (c + 1) % NSTAGE);
            CP_ASYNC_WAIT(1);
        } else {
            CP_ASYNC_WAIT(0);
        }
        __syncthreads();

        const uint32_t As_u = smem_u + stage * STAGE_BYTES;
        const uint32_t Bs_u = As_u + SA_BYTES;
        const uint32_t a_base = As_u + (m0 + a_row) * CROW_BYTES + a_kof * 2;
        const uint32_t b_base = Bs_u + (n0 + b_row) * CROW_BYTES + b_kof * 2;

        uint32_t bbf[2][2][4];   // [ks&1][nb]
        uint32_t aa[2][4];       // [mi&1]

        #pragma unroll
        for (int nb = 0; nb < 2; nb++)
            ldsm_x4(bbf[0][nb], b_base + nb * 16 * CROW_BYTES);

        #pragma unroll
        for (int ks = 0; ks < CHUNK_K / 16; ks++) {
            const uint32_t kbase = (uint32_t)ks * 32;
            const int cur = ks & 1;
            ldsm_x4(aa[0], a_base + kbase);
            #pragma unroll
            for (int mi = 0; mi < 4; mi++) {
                if (mi < 3) {
                    ldsm_x4(aa[(mi + 1) & 1], a_base + (mi + 1) * 16 * CROW_BYTES + kbase);
                } else if (ks < 3) {
                    #pragma unroll
                    for (int nb = 0; nb < 2; nb++)
                        ldsm_x4(bbf[(ks + 1) & 1][nb],
                                b_base + nb * 16 * CROW_BYTES + kbase + 32);
                }
                #pragma unroll
                for (int ni = 0; ni < 4; ni++) {
                    int nb = ni >> 1, hi = ni & 1;
                    mma_16816_bf16(acc[mi][ni], aa[mi & 1],
                                   bbf[cur][nb][hi * 2], bbf[cur][nb][hi * 2 + 1]);
                }
            }
        }
    }
    __syncthreads();   // all MMAs done before smem is reused as transpose buffer

    // ---- epilogue: e = exp(-(sqi+sqj-2g)/2s^2); direct store; keep e in acc --
    const float inv = g_inv;
    #pragma unroll
    for (int mi = 0; mi < 4; mi++) {
        const int rl0 = m0 + mi * 16 + (lane >> 2);
        const int gi  = row0 + rl0;
        const float sqi0 = g_sq[gi];
        const float sqi8 = g_sq[gi + 8];
        #pragma unroll
        for (int ni = 0; ni < 4; ni++) {
            const int cl = n0 + ni * 8 + ((lane & 3) << 1);
            const int gj = col0 + cl;
            const float2 sj = *reinterpret_cast<const float2*>(&g_sq[gj]);
            acc[mi][ni][0] = __expf(-fmaxf(sqi0 + sj.x - 2.f * acc[mi][ni][0], 0.f) * inv);
            acc[mi][ni][1] = __expf(-fmaxf(sqi0 + sj.y - 2.f * acc[mi][ni][1], 0.f) * inv);
            acc[mi][ni][2] = __expf(-fmaxf(sqi8 + sj.x - 2.f * acc[mi][ni][2], 0.f) * inv);
            acc[mi][ni][3] = __expf(-fmaxf(sqi8 + sj.y - 2.f * acc[mi][ni][3], 0.f) * inv);
        }
        #pragma unroll
        for (int ni = 0; ni < 4; ni++) {
            const int cl = n0 + ni * 8 + ((lane & 3) << 1);
            const int gj = col0 + cl;
            *reinterpret_cast<float2*>(&d_out[(size_t)gi * N_DIM + gj]) =
                make_float2(acc[mi][ni][0], acc[mi][ni][1]);
            *reinterpret_cast<float2*>(&d_out[(size_t)(gi + 8) * N_DIM + gj]) =
                make_float2(acc[mi][ni][2], acc[mi][ni][3]);
        }
    }

    // ---- mirror store in two 128-row phases through smem transpose buffer ----
    if (mirror) {
        float* trans = reinterpret_cast<float*>(smem);
        #pragma unroll 1
        for (int p = 0; p < 2; p++) {
            if ((warp_m >> 1) == p) {
                const int rh_base = (warp_m & 1) * 64 + (lane >> 2);
                #pragma unroll
                for (int mi = 0; mi < 4; mi++) {
                    const int rh = rh_base + mi * 16;
                    #pragma unroll
                    for (int ni = 0; ni < 4; ni++) {
                        const int cl = n0 + ni * 8 + ((lane & 3) << 1);
                        trans[(cl)     * T_ST + rh]     = acc[mi][ni][0];
                        trans[(cl + 1) * T_ST + rh]     = acc[mi][ni][1];
                        trans[(cl)     * T_ST + rh + 8] = acc[mi][ni][2];
                        trans[(cl + 1) * T_ST + rh + 8] = acc[mi][ni][3];
                    }
                }
            }
            __syncthreads();
            #pragma unroll
            for (int it = 0; it < 8; it++) {
                int e4 = tid + it * NTHREADS;
                int r  = e4 >> 5;
                int c4 = e4 & 31;
                const float* src = &trans[r * T_ST + c4 * 4];
                float4 v = make_float4(src[0], src[1], src[2], src[3]);
                *reinterpret_cast<float4*>(
                    &d_out[(size_t)(col0 + r) * N_DIM + row0 + p * 128 + c4 * 4]) = v;
            }
            __syncthreads();
        }
    }
}

// ---------------- launcher ----------------
extern "C" void kernel_launch(void* const* d_in, const int* in_sizes, int n_in,
                              void* d_out, int out_size) {
    const float* x = (const float*)d_in[0];
    float* out = (float*)d_out;

    static bool attr_set = false;
    if (!attr_set) {
        cudaFuncSetAttribute(gemm_fused_kernel,
                             cudaFuncAttributeMaxDynamicSharedMemorySize, GEMM_SMEM);
        attr_set = true;
    }

    prep_kernel<<<256, 512>>>(x);
    sigma_kernel<<<1, 1024>>>();
    gemm_fused_kernel<<<NUM_CTAS, NTHREADS, GEMM_SMEM>>>(out);
}